// round 3
// baseline (speedup 1.0000x reference)
#include <cuda_runtime.h>
#include <math.h>

#define Bc 2
#define C1 64
#define C4 256
#define Hh 64
#define Ww 96
#define HW (Hh*Ww)          // 6144
#define NC4 (Bc*C4*HW)      // 3145728
#define NC1 (Bc*C1*HW)      // 786432
#define Pp 4

// ---------------- scratch (device globals; no allocations allowed) ----------
__device__ float g_y0L[NC4];
__device__ float g_y0R[NC4];
__device__ float g_t1L[NC4];
__device__ float g_t1R[NC4];
__device__ float g_y2L[NC4];
__device__ float g_y2R[NC4];
__device__ float g_Q[NC1];   // layout (b, h*w, c)  -- NHWC for contiguous dots
__device__ float g_K[NC1];   // layout (b, h*w, c)

// ---------------- BN (eval) on both catfea tensors --------------------------
__global__ void bn_kernel(const float* __restrict__ catL, const float* __restrict__ catR,
                          const float* __restrict__ g, const float* __restrict__ bt,
                          const float* __restrict__ m, const float* __restrict__ v,
                          float* __restrict__ outL, float* __restrict__ outR) {
    int idx = blockIdx.x * blockDim.x + threadIdx.x;
    if (idx >= NC4) return;
    int c = (idx / HW) & (C4 - 1);
    float s  = g[c] * rsqrtf(v[c] + 1e-5f);
    float sh = bt[c] - m[c] * s;
    outL[idx] = catL[idx] * s + sh;
    outR[idx] = catR[idx] * s + sh;
}

// ---------------- grouped 3x3 conv (groups=4), pad 1 ------------------------
// MODE 1: out = leaky_relu(conv + bias, 0.1)
// MODE 2: out = conv + bias + res
// grid: x = W/32 (3), y = H/8 (8), z = side*32 + b*16 + octile(16)
// block: 256 threads: wq = tid&7 (4-wide w quad), hy = (tid>>3)&7, oq = tid>>6 (4 oc)
template<int MODE>
__global__ void conv3x3_kernel(const float* __restrict__ inL, const float* __restrict__ inR,
                               const float* __restrict__ wgt, const float* __restrict__ bias,
                               const float* __restrict__ resL, const float* __restrict__ resR,
                               float* __restrict__ outL, float* __restrict__ outR) {
    int z = blockIdx.z;
    int octile = z & 15;
    int b      = (z >> 4) & 1;
    int side   = z >> 5;
    const float* in  = side ? inR  : inL;
    const float* res = side ? resR : resL;
    float*       out = side ? outR : outL;
    int group = octile >> 2;                 // (octile*16)/64
    int h0 = blockIdx.y * 8, w0 = blockIdx.x * 32;

    __shared__ float sx[8][10][36];          // 8 ic x (8+2) rows x (32+2 valid, pitch 36)
    __shared__ float sw[8][9][16];           // 8 ic x 9 taps x 16 oc

    int tid = threadIdx.x;
    int wq = tid & 7, hy = (tid >> 3) & 7, oq = tid >> 6;

    float acc[4][4];
#pragma unroll
    for (int j = 0; j < 4; j++)
#pragma unroll
        for (int i = 0; i < 4; i++) acc[j][i] = 0.f;

    const float* inb = in + ((size_t)b * C4 + group * 64) * HW;

    for (int icc = 0; icc < 8; icc++) {
        // stage input chunk
        for (int t = tid; t < 8 * 10 * 34; t += 256) {
            int col = t % 34;
            int rr  = (t / 34) % 10;
            int ic  = t / 340;
            int hh = h0 - 1 + rr, ww = w0 - 1 + col;
            float vv = 0.f;
            if (hh >= 0 && hh < Hh && ww >= 0 && ww < Ww)
                vv = inb[(icc * 8 + ic) * HW + hh * Ww + ww];
            sx[ic][rr][col] = vv;
        }
        // stage weights: wgt[o][i][kh][kw], o = octile*16+oc, i = icc*8+ic
        for (int t = tid; t < 8 * 9 * 16; t += 256) {
            int oc = t & 15;
            int k  = (t >> 4) % 9;
            int ic = t / 144;
            sw[ic][k][oc] = wgt[(octile * 16 + oc) * 576 + (icc * 8 + ic) * 9 + k];
        }
        __syncthreads();

#pragma unroll
        for (int ic = 0; ic < 8; ic++) {
#pragma unroll
            for (int kh = 0; kh < 3; kh++) {
                float xr[6];
                float4 x4 = *(const float4*)&sx[ic][hy + kh][wq * 4];
                xr[0] = x4.x; xr[1] = x4.y; xr[2] = x4.z; xr[3] = x4.w;
                xr[4] = sx[ic][hy + kh][wq * 4 + 4];
                xr[5] = sx[ic][hy + kh][wq * 4 + 5];
#pragma unroll
                for (int kw = 0; kw < 3; kw++) {
                    float4 w4 = *(const float4*)&sw[ic][kh * 3 + kw][oq * 4];
                    float wv[4] = {w4.x, w4.y, w4.z, w4.w};
#pragma unroll
                    for (int j = 0; j < 4; j++)
#pragma unroll
                        for (int i = 0; i < 4; i++)
                            acc[j][i] = fmaf(wv[j], xr[kw + i], acc[j][i]);
                }
            }
        }
        __syncthreads();
    }

    int hh_o = h0 + hy, wwb = w0 + wq * 4;
#pragma unroll
    for (int j = 0; j < 4; j++) {
        int oc = octile * 16 + oq * 4 + j;
        float bv = bias[oc];
        size_t obase = ((size_t)b * C4 + oc) * HW + (size_t)hh_o * Ww + wwb;
        float4 o4;
        if (MODE == 1) {
            float v0 = acc[j][0] + bv, v1 = acc[j][1] + bv, v2 = acc[j][2] + bv, v3 = acc[j][3] + bv;
            o4.x = v0 > 0.f ? v0 : 0.1f * v0;
            o4.y = v1 > 0.f ? v1 : 0.1f * v1;
            o4.z = v2 > 0.f ? v2 : 0.1f * v2;
            o4.w = v3 > 0.f ? v3 : 0.1f * v3;
        } else {
            float4 r4 = *(const float4*)(res + obase);
            o4.x = acc[j][0] + bv + r4.x;
            o4.y = acc[j][1] + bv + r4.y;
            o4.z = acc[j][2] + bv + r4.z;
            o4.w = acc[j][3] + bv + r4.w;
        }
        *(float4*)(out + obase) = o4;
    }
}

// ---------------- grouped 1x1 conv (256 -> 64, groups=4), NHWC output -------
// blockIdx.x = ((side*2 + b)*4 + gq)*24 + pb ; px = pb*256 + tid
__global__ void conv1x1_kernel(const float* __restrict__ wq_, const float* __restrict__ bq,
                               const float* __restrict__ ws_, const float* __restrict__ bs) {
    int bx = blockIdx.x;
    int pb   = bx % 24;
    int gq   = (bx / 24) & 3;
    int b    = (bx / 96) & 1;
    int side = bx / 192;
    int px = pb * 256 + threadIdx.x;

    const float* in   = (side ? g_y2R : g_y2L) + ((size_t)b * C4 + gq * 64) * HW + px;
    const float* wgt  = side ? ws_ : wq_;
    const float* bias = side ? bs  : bq;
    float* out = (side ? g_K : g_Q) + ((size_t)b * HW + px) * 64 + gq * 16;

    __shared__ float sw_s[64][16];
    for (int t = threadIdx.x; t < 1024; t += 256) {
        int i = t >> 4, j = t & 15;
        sw_s[i][j] = wgt[(gq * 16 + j) * 64 + i];
    }
    __syncthreads();

    float acc[16];
#pragma unroll
    for (int j = 0; j < 16; j++) acc[j] = bias[gq * 16 + j];
#pragma unroll 4
    for (int i = 0; i < 64; i++) {
        float xv = in[(size_t)i * HW];
#pragma unroll
        for (int j = 0; j < 16; j++) acc[j] = fmaf(sw_s[i][j], xv, acc[j]);
    }
#pragma unroll
    for (int j = 0; j < 16; j++) out[j] = acc[j];
}

// ---------------- windowed cross-attention + output -------------------------
// one block per pixel, 64 threads (window positions / channels)
__global__ void attn_kernel(const float* __restrict__ xl, const float* __restrict__ xr,
                            const int* __restrict__ dLp, const int* __restrict__ dRp,
                            float* __restrict__ outL, float* __restrict__ outR) {
    int w = blockIdx.x, h = blockIdx.y, b = blockIdx.z;
    int tid = threadIdx.x;

    __shared__ float sq[64], sk[64], aR[64], aL[64], mRs[64], mLs[64];
    __shared__ int coord[64];

    int d_l = dLp[(b * Hh + h) * Ww + w];
    int d_r = dRp[(b * Hh + h) * Ww + w];
    int cR = max(w - d_l, 0);
    int cL = min(w + d_r, Ww - 1);
    bool validR = (h < Hh - Pp) && (cR < Ww - Pp);
    bool validL = (h < Hh - Pp) && (cL < Ww - Pp);
    float VL = (w - d_l >= 0)      ? 1.f : 0.f;
    float VR = (w + d_r <= Ww - 1) ? 1.f : 0.f;

    const float* Qb = g_Q + (size_t)b * HW * 64;
    const float* Kb = g_K + (size_t)b * HW * 64;
    sq[tid] = Qb[(h * Ww + w) * 64 + tid];
    sk[tid] = Kb[(h * Ww + w) * 64 + tid];

    int dh = tid >> 3, dw = tid & 7;
    int hh  = h + dh - Pp;
    int wwR = cR + dw - Pp;
    int wwL = cL + dw - Pp;
    bool inR = validR && (hh >= 0) && (hh < Hh) && (wwR >= 0) && (wwR < Ww);
    bool inL = validL && (hh >= 0) && (hh < Hh) && (wwL >= 0) && (wwL < Ww);
    coord[tid] = inR ? (hh * Ww + wwR) : -1;
    __syncthreads();

    // raw scores (mean-subtraction dropped: softmax shift-invariant)
    float s_r = 0.f, s_l = 0.f;
    if (inR) {
        const float4* kp = (const float4*)(Kb + (size_t)(hh * Ww + wwR) * 64);
#pragma unroll
        for (int c4 = 0; c4 < 16; c4++) {
            float4 kv = kp[c4];
            s_r += sq[4 * c4] * kv.x + sq[4 * c4 + 1] * kv.y
                 + sq[4 * c4 + 2] * kv.z + sq[4 * c4 + 3] * kv.w;
        }
    }
    if (inL) {
        const float4* qp = (const float4*)(Qb + (size_t)(hh * Ww + wwL) * 64);
#pragma unroll
        for (int c4 = 0; c4 < 16; c4++) {
            float4 qv = qp[c4];
            s_l += sk[4 * c4] * qv.x + sk[4 * c4 + 1] * qv.y
                 + sk[4 * c4 + 2] * qv.z + sk[4 * c4 + 3] * qv.w;
        }
    }
    aR[tid] = s_r; aL[tid] = s_l;
    __syncthreads();

    float mxR = -1e30f, mxL = -1e30f;
#pragma unroll 8
    for (int k = 0; k < 64; k++) { mxR = fmaxf(mxR, aR[k]); mxL = fmaxf(mxL, aL[k]); }
    float eR = expf(s_r - mxR), eL = expf(s_l - mxL);
    __syncthreads();
    aR[tid] = eR; aL[tid] = eL;
    __syncthreads();
    float smR = 0.f, smL = 0.f;
#pragma unroll 8
    for (int k = 0; k < 64; k++) { smR += aR[k]; smL += aL[k]; }
    mRs[tid] = eR / smR;
    mLs[tid] = eL / smL;
    __syncthreads();

    // value transfer: BOTH gathers use wr2l coords (faithful to source)
    float accL = 0.f, accR = 0.f;
    size_t cb = ((size_t)b * C1 + tid) * HW;
#pragma unroll 8
    for (int k = 0; k < 64; k++) {
        int o = coord[k];
        if (o >= 0) {
            accL += mRs[k] * xr[cb + o];
            accR += mLs[k] * xl[cb + o];
        }
    }
    size_t oidx = cb + (size_t)h * Ww + w;
    outL[oidx] = xl[oidx] + VL * accL;
    outR[oidx] = xr[oidx] + VR * accR;
}

// ---------------- launcher ---------------------------------------------------
extern "C" void kernel_launch(void* const* d_in, const int* in_sizes, int n_in,
                              void* d_out, int out_size) {
    const float* x_left  = (const float*)d_in[0];
    const float* x_right = (const float*)d_in[1];
    const float* catL    = (const float*)d_in[2];
    const float* catR    = (const float*)d_in[3];

    // Disambiguate metadata ordering (dict order vs signature order) by size.
    const int *dL, *dR;
    int pb;
    if (in_sizes[4] == Bc * Hh * Ww) {      // d_left/d_right at 4,5
        dL = (const int*)d_in[4];
        dR = (const int*)d_in[5];
        pb = 6;
    } else {                                 // d_left/d_right at 16,17
        dL = (const int*)d_in[16];
        dR = (const int*)d_in[17];
        pb = 4;
    }
    const float* bn_g = (const float*)d_in[pb + 0];
    const float* bn_b = (const float*)d_in[pb + 1];
    const float* bn_m = (const float*)d_in[pb + 2];
    const float* bn_v = (const float*)d_in[pb + 3];
    const float* rw1  = (const float*)d_in[pb + 4];
    const float* rb1  = (const float*)d_in[pb + 5];
    const float* rw2  = (const float*)d_in[pb + 6];
    const float* rb2  = (const float*)d_in[pb + 7];
    const float* bqw  = (const float*)d_in[pb + 8];
    const float* bqb  = (const float*)d_in[pb + 9];
    const float* bsw  = (const float*)d_in[pb + 10];
    const float* bsb  = (const float*)d_in[pb + 11];

    float *y0L, *y0R, *t1L, *t1R, *y2L, *y2R;
    cudaGetSymbolAddress((void**)&y0L, g_y0L);
    cudaGetSymbolAddress((void**)&y0R, g_y0R);
    cudaGetSymbolAddress((void**)&t1L, g_t1L);
    cudaGetSymbolAddress((void**)&t1R, g_t1R);
    cudaGetSymbolAddress((void**)&y2L, g_y2L);
    cudaGetSymbolAddress((void**)&y2R, g_y2R);

    bn_kernel<<<(NC4 + 255) / 256, 256>>>(catL, catR, bn_g, bn_b, bn_m, bn_v, y0L, y0R);

    dim3 cgrid(Ww / 32, Hh / 8, 64);
    conv3x3_kernel<1><<<cgrid, 256>>>(y0L, y0R, rw1, rb1, nullptr, nullptr, t1L, t1R);
    conv3x3_kernel<2><<<cgrid, 256>>>(t1L, t1R, rw2, rb2, y0L, y0R, y2L, y2R);

    conv1x1_kernel<<<384, 256>>>(bqw, bqb, bsw, bsb);

    float* outL = (float*)d_out;
    float* outR = outL + NC1;
    attn_kernel<<<dim3(Ww, Hh, Bc), 64>>>(x_left, x_right, dL, dR, outL, outR);
}

// round 6
// speedup vs baseline: 1.1672x; 1.1672x over previous
#include <cuda_runtime.h>
#include <math.h>
#include <stdint.h>

#define Bc 2
#define C1 64
#define C4 256
#define Hh 64
#define Ww 96
#define HW (Hh*Ww)          // 6144
#define NC4 (Bc*C4*HW)      // 3145728
#define NC1 (Bc*C1*HW)      // 786432
#define Pp 4

// ---------------- scratch (device globals; no allocations allowed) ----------
__device__ float g_y0L[NC4];
__device__ float g_y0R[NC4];
__device__ float g_t1L[NC4];
__device__ float g_t1R[NC4];
__device__ float g_y2L[NC4];
__device__ float g_y2R[NC4];
__device__ float g_Q[NC1];    // (b, h*w, c) NHWC
__device__ float g_K[NC1];    // (b, h*w, c) NHWC
__device__ float g_xlT[NC1];  // x_left  NHWC
__device__ float g_xrT[NC1];  // x_right NHWC

// ---- packed f32x2 helpers (Blackwell FFMA2: 2x fp32 throughput) ------------
__device__ __forceinline__ void fma2(unsigned long long& d, unsigned long long a,
                                     unsigned long long b) {
    asm("fma.rn.f32x2 %0, %1, %2, %0;" : "+l"(d) : "l"(a), "l"(b));
}
__device__ __forceinline__ unsigned long long pk(float lo, float hi) {
    unsigned long long p;
    asm("mov.b64 %0, {%1, %2};" : "=l"(p) : "f"(lo), "f"(hi));
    return p;
}
__device__ __forceinline__ void upk(unsigned long long v, float& lo, float& hi) {
    asm("mov.b64 {%0, %1}, %2;" : "=f"(lo), "=f"(hi) : "l"(v));
}

// ---------------- BN (eval) on both catfea tensors --------------------------
__global__ void bn_kernel(const float* __restrict__ catL, const float* __restrict__ catR,
                          const float* __restrict__ g, const float* __restrict__ bt,
                          const float* __restrict__ m, const float* __restrict__ v,
                          float* __restrict__ outL, float* __restrict__ outR) {
    int idx = blockIdx.x * blockDim.x + threadIdx.x;
    if (idx >= NC4) return;
    int c = (idx / HW) & (C4 - 1);
    float s  = g[c] * rsqrtf(v[c] + 1e-5f);
    float sh = bt[c] - m[c] * s;
    outL[idx] = catL[idx] * s + sh;
    outR[idx] = catR[idx] * s + sh;
}

// ---------------- NCHW -> NHWC transpose of x_left / x_right ---------------
__global__ void transpose_kernel(const float* __restrict__ xl, const float* __restrict__ xr) {
    __shared__ float t[64][33];
    int z = blockIdx.z;
    int side = z >> 1, b = z & 1;
    const float* src = side ? xr : xl;
    float* dst = side ? g_xrT : g_xlT;
    int h = blockIdx.y, w0 = blockIdx.x * 32;
    int tid = threadIdx.x;
#pragma unroll
    for (int i = 0; i < 8; i++) {
        int c = i * 8 + (tid >> 5);
        t[c][tid & 31] = src[((size_t)b * C1 + c) * HW + h * Ww + w0 + (tid & 31)];
    }
    __syncthreads();
#pragma unroll
    for (int it = 0; it < 8; it++) {
        int idx = it * 256 + tid;
        int c = idx & 63, wl = idx >> 6;
        dst[((size_t)b * HW + h * Ww + w0 + wl) * 64 + c] = t[c][wl];
    }
}

// ---------------- grouped 3x3 conv (groups=4), pad 1, f32x2 packed ----------
// MODE 1: leaky_relu(conv+bias, 0.1); MODE 2: conv+bias+res
// grid: x=3 (32w), y=8 (8h), z=32: [side:1][b:1][group:2][half:1]
// block 256: wq=tid&7 (4 w), hy=(tid>>3)&7, oq=tid>>6 (8 oc each)
template<int MODE>
__global__ void conv3x3_kernel(const float* __restrict__ inL, const float* __restrict__ inR,
                               const float* __restrict__ wgt, const float* __restrict__ bias,
                               const float* __restrict__ resL, const float* __restrict__ resR,
                               float* __restrict__ outL, float* __restrict__ outR) {
    int z = blockIdx.z;
    int side  = z >> 4;
    int b     = (z >> 3) & 1;
    int group = (z >> 1) & 3;
    int half  = z & 1;
    int ocb = group * 64 + half * 32;
    const float* in  = side ? inR  : inL;
    const float* res = side ? resR : resL;
    float*       out = side ? outR : outL;
    int h0 = blockIdx.y * 8, w0 = blockIdx.x * 32;

    __shared__ float sx[8][10][37];                 // scalar LDS only; banks 5*hy+4*wq+i distinct
    __shared__ __align__(16) float2 sw2[8][9][32];  // 16B-aligned for ulonglong2 loads

    int tid = threadIdx.x;
    int wq = tid & 7, hy = (tid >> 3) & 7, oq = tid >> 6;

    unsigned long long acc[8][2];
#pragma unroll
    for (int j = 0; j < 8; j++) { acc[j][0] = 0ULL; acc[j][1] = 0ULL; }

    const float* inb = in + ((size_t)b * C4 + group * 64) * HW;

    for (int icc = 0; icc < 8; icc++) {
        // stage input chunk (8 ic x 10 rows x 34 cols)
        for (int t = tid; t < 8 * 10 * 34; t += 256) {
            int col = t % 34;
            int rr  = (t / 34) % 10;
            int ic  = t / 340;
            int hh = h0 - 1 + rr, ww = w0 - 1 + col;
            float vv = 0.f;
            if (hh >= 0 && hh < Hh && ww >= 0 && ww < Ww)
                vv = inb[(icc * 8 + ic) * HW + hh * Ww + ww];
            sx[ic][rr][col] = vv;
        }
        // stage weights (8 ic x 9 taps x 32 oc), duplicated pairs
        for (int t = tid; t < 8 * 9 * 32; t += 256) {
            int oc = t & 31;
            int k  = (t >> 5) % 9;
            int ic = t / 288;
            float v = wgt[(size_t)(ocb + oc) * 576 + (icc * 8 + ic) * 9 + k];
            sw2[ic][k][oc] = make_float2(v, v);
        }
        __syncthreads();

#pragma unroll
        for (int ic = 0; ic < 8; ic++) {
#pragma unroll
            for (int kh = 0; kh < 3; kh++) {
                float x6[6];
#pragma unroll
                for (int i = 0; i < 6; i++)   // scalar LDS: aligned + conflict-free
                    x6[i] = sx[ic][hy + kh][wq * 4 + i];
                unsigned long long pa[3], pb[3];
                pa[0] = pk(x6[0], x6[1]);
                pa[1] = pk(x6[1], x6[2]);
                pa[2] = pk(x6[2], x6[3]);
                pb[0] = pa[2];
                pb[1] = pk(x6[3], x6[4]);
                pb[2] = pk(x6[4], x6[5]);
#pragma unroll
                for (int kw = 0; kw < 3; kw++) {
                    const ulonglong2* wp = (const ulonglong2*)&sw2[ic][kh * 3 + kw][oq * 8];
                    ulonglong2 wA = wp[0], wB = wp[1], wC = wp[2], wD = wp[3];
                    unsigned long long A = pa[kw], B = pb[kw];
                    fma2(acc[0][0], A, wA.x); fma2(acc[0][1], B, wA.x);
                    fma2(acc[1][0], A, wA.y); fma2(acc[1][1], B, wA.y);
                    fma2(acc[2][0], A, wB.x); fma2(acc[2][1], B, wB.x);
                    fma2(acc[3][0], A, wB.y); fma2(acc[3][1], B, wB.y);
                    fma2(acc[4][0], A, wC.x); fma2(acc[4][1], B, wC.x);
                    fma2(acc[5][0], A, wC.y); fma2(acc[5][1], B, wC.y);
                    fma2(acc[6][0], A, wD.x); fma2(acc[6][1], B, wD.x);
                    fma2(acc[7][0], A, wD.y); fma2(acc[7][1], B, wD.y);
                }
            }
        }
        __syncthreads();
    }

    int hh_o = h0 + hy, wwb = w0 + wq * 4;
#pragma unroll
    for (int j = 0; j < 8; j++) {
        int oc = ocb + oq * 8 + j;
        float bv = bias[oc];
        float a0, a1, a2, a3;
        upk(acc[j][0], a0, a1);
        upk(acc[j][1], a2, a3);
        size_t obase = ((size_t)b * C4 + oc) * HW + (size_t)hh_o * Ww + wwb;
        float4 o4;
        if (MODE == 1) {
            float v0 = a0 + bv, v1 = a1 + bv, v2 = a2 + bv, v3 = a3 + bv;
            o4.x = v0 > 0.f ? v0 : 0.1f * v0;
            o4.y = v1 > 0.f ? v1 : 0.1f * v1;
            o4.z = v2 > 0.f ? v2 : 0.1f * v2;
            o4.w = v3 > 0.f ? v3 : 0.1f * v3;
        } else {
            float4 r4 = *(const float4*)(res + obase);
            o4.x = a0 + bv + r4.x;
            o4.y = a1 + bv + r4.y;
            o4.z = a2 + bv + r4.z;
            o4.w = a3 + bv + r4.w;
        }
        *(float4*)(out + obase) = o4;
    }
}

// ---------------- grouped 1x1 conv (256 -> 64, groups=4), NHWC output -------
__global__ void conv1x1_kernel(const float* __restrict__ wq_, const float* __restrict__ bq,
                               const float* __restrict__ ws_, const float* __restrict__ bs) {
    int bx = blockIdx.x;
    int pb   = bx % 24;
    int gq   = (bx / 24) & 3;
    int b    = (bx / 96) & 1;
    int side = bx / 192;
    int px = pb * 256 + threadIdx.x;

    const float* in   = (side ? g_y2R : g_y2L) + ((size_t)b * C4 + gq * 64) * HW + px;
    const float* wgt  = side ? ws_ : wq_;
    const float* bias = side ? bs  : bq;
    float* out = (side ? g_K : g_Q) + ((size_t)b * HW + px) * 64 + gq * 16;

    __shared__ float sw_s[64][16];
    for (int t = threadIdx.x; t < 1024; t += 256) {
        int i = t >> 4, j = t & 15;
        sw_s[i][j] = wgt[(gq * 16 + j) * 64 + i];
    }
    __syncthreads();

    float acc[16];
#pragma unroll
    for (int j = 0; j < 16; j++) acc[j] = bias[gq * 16 + j];
#pragma unroll 8
    for (int i = 0; i < 64; i++) {
        float xv = in[(size_t)i * HW];
#pragma unroll
        for (int j = 0; j < 16; j++) acc[j] = fmaf(sw_s[i][j], xv, acc[j]);
    }
#pragma unroll
    for (int j = 0; j < 16; j++) out[j] = acc[j];
}

// ---------------- windowed cross-attention + output (coalesced) -------------
// one pixel per 128-thread block
__global__ void attn_kernel(const float* __restrict__ xl, const float* __restrict__ xr,
                            const int* __restrict__ dLp, const int* __restrict__ dRp,
                            float* __restrict__ outL, float* __restrict__ outR) {
    int w = blockIdx.x, h = blockIdx.y, b = blockIdx.z;
    int tid = threadIdx.x;

    __shared__ __align__(16) float Kp[64][68];  // pitch 68: 16B-aligned rows, phase-conflict-free
    __shared__ __align__(16) float Qp[64][68];
    __shared__ float sq[64], sk[64];
    __shared__ float sc[2][64], prob[2][64];
    __shared__ int crd[2][64];   // [0] = r2l coords, [1] = l2r coords

    int d_l = dLp[(b * Hh + h) * Ww + w];
    int d_r = dRp[(b * Hh + h) * Ww + w];
    int cR = max(w - d_l, 0);
    int cL = min(w + d_r, Ww - 1);
    bool validR = (h < Hh - Pp) && (cR < Ww - Pp);
    bool validL = (h < Hh - Pp) && (cL < Ww - Pp);

    const float* Qb = g_Q + (size_t)b * HW * 64;
    const float* Kb = g_K + (size_t)b * HW * 64;

    {
        int k = tid & 63;
        if (tid < 64) {
            sq[k] = Qb[(size_t)(h * Ww + w) * 64 + k];
            int dh = k >> 3, dw = k & 7;
            int hh = h + dh - Pp;
            int wwR = cR + dw - Pp;
            int wwL = cL + dw - Pp;
            bool inR = validR && (hh >= 0) && (hh < Hh) && (wwR >= 0) && (wwR < Ww);
            bool inL = validL && (hh >= 0) && (hh < Hh) && (wwL >= 0) && (wwL < Ww);
            crd[0][k] = inR ? (hh * Ww + wwR) : -1;
            crd[1][k] = inL ? (hh * Ww + wwL) : -1;
        } else {
            sk[k] = Kb[(size_t)(h * Ww + w) * 64 + k];
        }
    }
    __syncthreads();

    // stage K-patch (r2l) and Q-patch (l2r), coalesced
    {
        int row8 = tid >> 4;          // 8 rows per pass
        int ch4  = (tid & 15) * 4;
        float4 z4 = make_float4(0.f, 0.f, 0.f, 0.f);
#pragma unroll
        for (int pass = 0; pass < 8; pass++) {
            int row = pass * 8 + row8;
            int oR = crd[0][row];
            *(float4*)&Kp[row][ch4] =
                (oR >= 0) ? *(const float4*)&Kb[(size_t)oR * 64 + ch4] : z4;
            int oL = crd[1][row];
            *(float4*)&Qp[row][ch4] =
                (oL >= 0) ? *(const float4*)&Qb[(size_t)oL * 64 + ch4] : z4;
        }
    }
    __syncthreads();

    int side = tid >> 6, k = tid & 63;
    // scores (mean-subtraction dropped: softmax shift-invariant)
    {
        const float* vec = side ? sk : sq;
        const float* P = side ? &Qp[k][0] : &Kp[k][0];
        float s = 0.f;
#pragma unroll
        for (int c4 = 0; c4 < 16; c4++) {
            float4 p = *(const float4*)&P[c4 * 4];
            s += vec[4 * c4] * p.x + vec[4 * c4 + 1] * p.y
               + vec[4 * c4 + 2] * p.z + vec[4 * c4 + 3] * p.w;
        }
        sc[side][k] = s;
    }
    __syncthreads();
    float sv = sc[side][k];
    float mx = -1e30f;
#pragma unroll 8
    for (int kk = 0; kk < 64; kk++) mx = fmaxf(mx, sc[side][kk]);
    float e = expf(sv - mx);
    prob[side][k] = e;
    __syncthreads();
    float sm = 0.f;
#pragma unroll 8
    for (int kk = 0; kk < 64; kk++) sm += prob[side][kk];
    sc[side][k] = e / sm;    // overwrite with softmax weight
    __syncthreads();

    // value transfer: BOTH gathers use r2l coords (faithful to source);
    // thread = channel, coalesced NHWC reads
    {
        int ch = k;                               // tid&63
        const float* xv = side ? g_xlT : g_xrT;   // side0 -> left out gathers right
        const float* wv = sc[side];
        float acc = 0.f;
#pragma unroll 4
        for (int kk = 0; kk < 64; kk++) {
            int o = crd[0][kk];
            if (o >= 0) acc += wv[kk] * xv[((size_t)b * HW + o) * 64 + ch];
        }
        size_t oidx = ((size_t)b * C1 + ch) * HW + (size_t)h * Ww + w;
        if (side == 0) {
            float VL = (w - d_l >= 0) ? 1.f : 0.f;
            outL[oidx] = xl[oidx] + VL * acc;
        } else {
            float VR = (w + d_r <= Ww - 1) ? 1.f : 0.f;
            outR[oidx] = xr[oidx] + VR * acc;
        }
    }
}

// ---------------- launcher ---------------------------------------------------
extern "C" void kernel_launch(void* const* d_in, const int* in_sizes, int n_in,
                              void* d_out, int out_size) {
    const float* x_left  = (const float*)d_in[0];
    const float* x_right = (const float*)d_in[1];
    const float* catL    = (const float*)d_in[2];
    const float* catR    = (const float*)d_in[3];

    const int *dL, *dR;
    int pb;
    if (in_sizes[4] == Bc * Hh * Ww) {
        dL = (const int*)d_in[4];
        dR = (const int*)d_in[5];
        pb = 6;
    } else {
        dL = (const int*)d_in[16];
        dR = (const int*)d_in[17];
        pb = 4;
    }
    const float* bn_g = (const float*)d_in[pb + 0];
    const float* bn_b = (const float*)d_in[pb + 1];
    const float* bn_m = (const float*)d_in[pb + 2];
    const float* bn_v = (const float*)d_in[pb + 3];
    const float* rw1  = (const float*)d_in[pb + 4];
    const float* rb1  = (const float*)d_in[pb + 5];
    const float* rw2  = (const float*)d_in[pb + 6];
    const float* rb2  = (const float*)d_in[pb + 7];
    const float* bqw  = (const float*)d_in[pb + 8];
    const float* bqb  = (const float*)d_in[pb + 9];
    const float* bsw  = (const float*)d_in[pb + 10];
    const float* bsb  = (const float*)d_in[pb + 11];

    float *y0L, *y0R, *t1L, *t1R, *y2L, *y2R;
    cudaGetSymbolAddress((void**)&y0L, g_y0L);
    cudaGetSymbolAddress((void**)&y0R, g_y0R);
    cudaGetSymbolAddress((void**)&t1L, g_t1L);
    cudaGetSymbolAddress((void**)&t1R, g_t1R);
    cudaGetSymbolAddress((void**)&y2L, g_y2L);
    cudaGetSymbolAddress((void**)&y2R, g_y2R);

    bn_kernel<<<(NC4 + 255) / 256, 256>>>(catL, catR, bn_g, bn_b, bn_m, bn_v, y0L, y0R);

    transpose_kernel<<<dim3(3, 64, 4), 256>>>(x_left, x_right);

    dim3 cgrid(3, 8, 32);
    conv3x3_kernel<1><<<cgrid, 256>>>(y0L, y0R, rw1, rb1, nullptr, nullptr, t1L, t1R);
    conv3x3_kernel<2><<<cgrid, 256>>>(t1L, t1R, rw2, rb2, y0L, y0R, y2L, y2R);

    conv1x1_kernel<<<384, 256>>>(bqw, bqb, bsw, bsb);

    float* outL = (float*)d_out;
    float* outR = outL + NC1;
    attn_kernel<<<dim3(Ww, Hh, Bc), 128>>>(x_left, x_right, dL, dR, outL, outR);
}